// round 7
// baseline (speedup 1.0000x reference)
#include <cuda_runtime.h>
#include <math.h>
#include <stdint.h>

#define BATCH 8
#define SEQ 1024
#define DIM 512
#define HEADS 16
#define HD 32
#define MROWS (BATCH*SEQ)   /* 8192 */
#define MLPH 2048
#define TBLN 3969           /* (2*32-1)^2 */

// ---------------- scratch (device globals; no allocations allowed) ----------
__device__ float g_h[MROWS * DIM];           // LN out (tf32, k-permuted)
__device__ float g_qkv[MROWS * 3 * DIM];     // q,k permuted; v plain (all tf32)
__device__ float g_attnout[MROWS * DIM];     // attention out (tf32, k-permuted)
__device__ float g_xres[MROWS * DIM];        // x + proj(attn)  (fp32, plain)
__device__ float g_mlp1[MROWS * MLPH];       // gelu(fc1) (tf32, k-permuted)
__device__ float g_w[3145728];               // transposed+permuted+rounded weights

#define W_QKV  0
#define W_PROJ 786432
#define W_FC1  1048576
#define W_FC2  2097152

// ---------------- helpers ----------------------------------------------------
__device__ __forceinline__ float to_tf32(float x) {
    uint32_t u;
    asm("cvt.rna.tf32.f32 %0, %1;" : "=r"(u) : "f"(x));
    return __uint_as_float(u);
}

__device__ __forceinline__ void mma_tf32(float* c, uint32_t a0, uint32_t a1,
                                         uint32_t a2, uint32_t a3,
                                         uint32_t b0, uint32_t b1) {
    asm volatile(
        "mma.sync.aligned.m16n8k8.row.col.f32.tf32.tf32.f32 "
        "{%0,%1,%2,%3}, {%4,%5,%6,%7}, {%8,%9}, {%0,%1,%2,%3};"
        : "+f"(c[0]), "+f"(c[1]), "+f"(c[2]), "+f"(c[3])
        : "r"(a0), "r"(a1), "r"(a2), "r"(a3), "r"(b0), "r"(b1));
}
#define U(x) __float_as_uint(x)

__device__ __forceinline__ void cp16(uint32_t s, const void* g) {
    asm volatile("cp.async.cg.shared.global [%0], [%1], 16;\n" :: "r"(s), "l"(g));
}
__device__ __forceinline__ void cp_commit() {
    asm volatile("cp.async.commit_group;\n");
}
template <int N> __device__ __forceinline__ void cp_wait() {
    asm volatile("cp.async.wait_group %0;\n" :: "n"(N));
}

// ---------------- weight transpose + 32-block k-permute + tf32 round --------
// in: [K][N] row-major.  out: [N][K], with k' = (k&3)*8 + (k>>2) inside each
// 32-block.  out[n][bk + c] = tf32(in[bk + 4*(c&7) + (c>>3)][n]).
__global__ void __launch_bounds__(256) cvt_t_kernel(const float* __restrict__ in,
                                                    float* __restrict__ out,
                                                    int K, int N)
{
    __shared__ float tile[32][33];
    const int bk = blockIdx.y * 32, bn = blockIdx.x * 32;
    const int tx = threadIdx.x, ty = threadIdx.y;
    #pragma unroll
    for (int i = 0; i < 4; i++)
        tile[ty + 8 * i][tx] = in[(size_t)(bk + ty + 8 * i) * N + bn + tx];
    __syncthreads();
    #pragma unroll
    for (int i = 0; i < 4; i++) {
        const int n = ty + 8 * i;
        out[(size_t)(bn + n) * K + bk + tx] =
            to_tf32(tile[4 * (tx & 7) + (tx >> 3)][n]);
    }
}

// ---------------- LayerNorm (tf32-rounded, k-permuted output) ---------------
__global__ void __launch_bounds__(128) ln_kernel(const float* __restrict__ x,
                                                 const float* __restrict__ g,
                                                 const float* __restrict__ b,
                                                 float* __restrict__ out)
{
    const int row = blockIdx.x;
    const int t = threadIdx.x;
    const float4 v = ((const float4*)(x + (size_t)row * DIM))[t];
    float s  = v.x + v.y + v.z + v.w;
    float s2 = v.x*v.x + v.y*v.y + v.z*v.z + v.w*v.w;
    #pragma unroll
    for (int o = 16; o > 0; o >>= 1) {
        s  += __shfl_xor_sync(0xffffffffu, s,  o);
        s2 += __shfl_xor_sync(0xffffffffu, s2, o);
    }
    __shared__ float rs[4], rs2[4];
    if ((t & 31) == 0) { rs[t >> 5] = s; rs2[t >> 5] = s2; }
    __syncthreads();
    s  = rs[0] + rs[1] + rs[2] + rs[3];
    s2 = rs2[0] + rs2[1] + rs2[2] + rs2[3];
    const float mean = s * (1.0f / DIM);
    const float var  = s2 * (1.0f / DIM) - mean * mean;
    const float inv  = rsqrtf(var + 1e-5f);
    const float4 gg = ((const float4*)g)[t];
    const float4 bb = ((const float4*)b)[t];
    float o4[4];
    o4[0] = to_tf32((v.x - mean) * inv * gg.x + bb.x);
    o4[1] = to_tf32((v.y - mean) * inv * gg.y + bb.y);
    o4[2] = to_tf32((v.z - mean) * inv * gg.z + bb.z);
    o4[3] = to_tf32((v.w - mean) * inv * gg.w + bb.w);
    // col 4t+c -> permuted (t>>3)*32 + 8c + (t&7)
    float* op = out + (size_t)row * DIM + (t >> 3) * 32 + (t & 7);
    #pragma unroll
    for (int c = 0; c < 4; c++) op[8 * c] = o4[c];
}

// ---------------- tf32 GEMM: permuted layouts, LDS.128 frags ----------------
// C[M,N] = epilogue(A[M,K] @ Wt[N,K]^T + bias [, R])
// A gmem: [M][K] k-permuted per 32-block.  Wt: [N][K] k-permuted.
// 128x128 block tile, BK=32, 256 thr = 8 warps (4x2), warp tile 32x64.
enum { EPI_BIAS = 0, EPI_GELU = 1, EPI_RES = 2 };
// PERM: 0 = plain fp32 out; 1 = permuted out; 2 = permuted iff col<1024 (qkv)

template <int EPI, int CVT, int PERM>
__global__ void __launch_bounds__(256, 2) gemm_tc(const float* __restrict__ A,
                                                  const float* __restrict__ Wt,
                                                  const float* __restrict__ bias,
                                                  const float* __restrict__ R,
                                                  float* __restrict__ C,
                                                  int M, int N, int K)
{
    __shared__ __align__(16) float As[2][128][36];   // [m][k']
    __shared__ __align__(16) float Bs[2][128][36];   // [n][k']

    const int bm = blockIdx.y * 128, bn = blockIdx.x * 128;
    const int tid = threadIdx.x;
    const int warp = tid >> 5, lane = tid & 31;
    const int wm = (warp & 3) * 32, wn = (warp >> 2) * 64;
    const int g = lane >> 2, t4 = lane & 3;

    // staging: fid = tid + i*256, i<4 per operand; row = fid>>3, kc = fid&7
    const int srow = tid >> 3, skc = (tid & 7) * 4;

    float acc[2][8][4];
    #pragma unroll
    for (int mi = 0; mi < 2; mi++)
        #pragma unroll
        for (int ni = 0; ni < 8; ni++)
            #pragma unroll
            for (int c = 0; c < 4; c++) acc[mi][ni][c] = 0.0f;

    const int nk = K >> 5;

    // prologue: stage 0
    #pragma unroll
    for (int i = 0; i < 4; i++) {
        const int r = srow + i * 32;
        cp16((uint32_t)__cvta_generic_to_shared(&As[0][r][skc]),
             A + (size_t)(bm + r) * K + skc);
        cp16((uint32_t)__cvta_generic_to_shared(&Bs[0][r][skc]),
             Wt + (size_t)(bn + r) * K + skc);
    }
    cp_commit();

    for (int kt = 0; kt < nk; kt++) {
        const int s = kt & 1;
        if (kt + 1 < nk) {
            const int k0 = (kt + 1) * 32, sn = s ^ 1;
            #pragma unroll
            for (int i = 0; i < 4; i++) {
                const int r = srow + i * 32;
                cp16((uint32_t)__cvta_generic_to_shared(&As[sn][r][skc]),
                     A + (size_t)(bm + r) * K + k0 + skc);
                cp16((uint32_t)__cvta_generic_to_shared(&Bs[sn][r][skc]),
                     Wt + (size_t)(bn + r) * K + k0 + skc);
            }
            cp_commit();
            cp_wait<1>();
        } else {
            cp_wait<0>();
        }
        __syncthreads();

        #pragma unroll
        for (int h2 = 0; h2 < 2; h2++) {
            const int kc = 8 * t4 + 4 * h2;
            float4 a4[2][2];
            #pragma unroll
            for (int mi = 0; mi < 2; mi++) {
                a4[mi][0] = *(const float4*)&As[s][wm + 16 * mi + g][kc];
                a4[mi][1] = *(const float4*)&As[s][wm + 16 * mi + g + 8][kc];
            }
            #pragma unroll
            for (int ni = 0; ni < 8; ni++) {
                const float4 b4 = *(const float4*)&Bs[s][wn + 8 * ni + g][kc];
                #pragma unroll
                for (int mi = 0; mi < 2; mi++) {
                    mma_tf32(acc[mi][ni], U(a4[mi][0].x), U(a4[mi][1].x),
                             U(a4[mi][0].y), U(a4[mi][1].y), U(b4.x), U(b4.y));
                    mma_tf32(acc[mi][ni], U(a4[mi][0].z), U(a4[mi][1].z),
                             U(a4[mi][0].w), U(a4[mi][1].w), U(b4.z), U(b4.w));
                }
            }
        }
        __syncthreads();
    }

    // epilogue
    #pragma unroll
    for (int mi = 0; mi < 2; mi++) {
        const int r0 = bm + wm + mi * 16 + g;
        #pragma unroll
        for (int ni = 0; ni < 8; ni++) {
            const int col = bn + wn + ni * 8 + t4 * 2;
            const float b0 = bias[col], b1 = bias[col + 1];
            float v[4];
            v[0] = acc[mi][ni][0] + b0;
            v[1] = acc[mi][ni][1] + b1;
            v[2] = acc[mi][ni][2] + b0;
            v[3] = acc[mi][ni][3] + b1;
            if (EPI == EPI_GELU) {
                #pragma unroll
                for (int c = 0; c < 4; c++)
                    v[c] = 0.5f * v[c] * (1.0f + erff(v[c] * 0.70710678118654752f));
            }
            if (EPI == EPI_RES) {
                const float2 r4a = *(const float2*)(R + (size_t)r0 * N + col);
                const float2 r4b = *(const float2*)(R + (size_t)(r0 + 8) * N + col);
                v[0] += r4a.x; v[1] += r4a.y;
                v[2] += r4b.x; v[3] += r4b.y;
            }
            if (CVT) {
                #pragma unroll
                for (int c = 0; c < 4; c++) v[c] = to_tf32(v[c]);
            }
            const bool perm = (PERM == 1) || (PERM == 2 && col < 1024);
            if (perm) {
                const int p = (col & ~31) + 16 * (t4 & 1) + 2 * (ni & 3) + (t4 >> 1);
                C[(size_t)r0 * N + p]           = v[0];
                C[(size_t)r0 * N + p + 8]       = v[1];
                C[(size_t)(r0 + 8) * N + p]     = v[2];
                C[(size_t)(r0 + 8) * N + p + 8] = v[3];
            } else {
                *(float2*)(C + (size_t)r0 * N + col)       = make_float2(v[0], v[1]);
                *(float2*)(C + (size_t)(r0 + 8) * N + col) = make_float2(v[2], v[3]);
            }
        }
    }
}

// ---------------- Flash attention: LDS.128 K-frags, smem bias table ---------
// Block: 128 queries x one (b,h); 8 warps x 16 q-rows; 64-key tiles.
// rel-pos index computed in closed form; per-head table column in smem.
__global__ void __launch_bounds__(256, 2) attn_tc_kernel(const float* __restrict__ table,
                                                         float* __restrict__ out)
{
    __shared__ __align__(16) float Ks[2][64][36];
    __shared__ __align__(16) float Vs[2][64][36];
    __shared__ float Ps[8][16][68];
    __shared__ float tbl[TBLN];

    const int b = blockIdx.z, h = blockIdx.y, q0 = blockIdx.x * 128;
    const int tid = threadIdx.x;
    const int warp = tid >> 5, lane = tid & 31;
    const int g = lane >> 2, t4 = lane & 3;
    const int wq = warp * 16;

    const float scale = 0.17677669529663687f; // 1/sqrt(32)

    // K/V staging map
    const int key0 = tid >> 3, c40 = (tid & 7) * 4;

    // prologue: stage tile 0 (start it before table loads)
    #pragma unroll
    for (int i = 0; i < 2; i++) {
        const int key = key0 + i * 32;
        const float* kp = g_qkv + ((size_t)(b * SEQ + key)) * (3 * DIM)
                          + DIM + h * HD + c40;
        cp16((uint32_t)__cvta_generic_to_shared(&Ks[0][key][c40]), kp);
        cp16((uint32_t)__cvta_generic_to_shared(&Vs[0][key][c40]), kp + DIM);
    }
    cp_commit();

    // per-head bias table column -> smem
    for (int i = tid; i < TBLN; i += 256) tbl[i] = table[i * HEADS + h];

    // ---- Q fragments: permuted gmem -> 4 float4 loads ----
    uint32_t qf[4][4];
    {
        const float* q0p = g_qkv + ((size_t)(b * SEQ + q0 + wq + g)) * (3 * DIM) + h * HD;
        const float* q1p = q0p + 8 * (3 * DIM);
        const float4 A0 = *(const float4*)(q0p + 8 * t4);
        const float4 A1 = *(const float4*)(q0p + 8 * t4 + 4);
        const float4 C0 = *(const float4*)(q1p + 8 * t4);
        const float4 C1 = *(const float4*)(q1p + 8 * t4 + 4);
        qf[0][0] = U(to_tf32(A0.x * scale)); qf[0][1] = U(to_tf32(C0.x * scale));
        qf[0][2] = U(to_tf32(A0.y * scale)); qf[0][3] = U(to_tf32(C0.y * scale));
        qf[1][0] = U(to_tf32(A0.z * scale)); qf[1][1] = U(to_tf32(C0.z * scale));
        qf[1][2] = U(to_tf32(A0.w * scale)); qf[1][3] = U(to_tf32(C0.w * scale));
        qf[2][0] = U(to_tf32(A1.x * scale)); qf[2][1] = U(to_tf32(C1.x * scale));
        qf[2][2] = U(to_tf32(A1.y * scale)); qf[2][3] = U(to_tf32(C1.y * scale));
        qf[3][0] = U(to_tf32(A1.z * scale)); qf[3][1] = U(to_tf32(C1.z * scale));
        qf[3][2] = U(to_tf32(A1.w * scale)); qf[3][3] = U(to_tf32(C1.w * scale));
    }

    // rel-index bases: ri = (ly - my)*63 + (lx - mx) + 1984
    const int l0 = q0 + wq + g, l1 = l0 + 8;
    const int Cb0 = (l0 >> 5) * 63 + (l0 & 31) + 1984;
    const int Cb1 = (l1 >> 5) * 63 + (l1 & 31) + 1984;

    float m0 = -1e30f, m1 = -1e30f, li0 = 0.0f, li1 = 0.0f;
    float acc_o[4][4];
    #pragma unroll
    for (int ni = 0; ni < 4; ni++)
        #pragma unroll
        for (int c = 0; c < 4; c++) acc_o[ni][c] = 0.0f;

    for (int it = 0; it < SEQ / 64; it++) {
        const int s = it & 1;
        const int k0 = it * 64;
        if (it + 1 < SEQ / 64) {
            const int sn = s ^ 1;
            #pragma unroll
            for (int i = 0; i < 2; i++) {
                const int key = key0 + i * 32;
                const float* kp = g_qkv + ((size_t)(b * SEQ + k0 + 64 + key)) * (3 * DIM)
                                  + DIM + h * HD + c40;
                cp16((uint32_t)__cvta_generic_to_shared(&Ks[sn][key][c40]), kp);
                cp16((uint32_t)__cvta_generic_to_shared(&Vs[sn][key][c40]), kp + DIM);
            }
            cp_commit();
            cp_wait<1>();
        } else {
            cp_wait<0>();
        }
        __syncthreads();

        // ---- S = Q @ K^T ----
        float sacc[8][4];
        #pragma unroll
        for (int ni = 0; ni < 8; ni++)
            #pragma unroll
            for (int c = 0; c < 4; c++) sacc[ni][c] = 0.0f;
        #pragma unroll
        for (int h2 = 0; h2 < 2; h2++) {
            const int kc = 8 * t4 + 4 * h2;
            #pragma unroll
            for (int ni = 0; ni < 8; ni++) {
                const float4 kf = *(const float4*)&Ks[s][ni * 8 + g][kc];
                mma_tf32(sacc[ni], qf[2*h2][0], qf[2*h2][1], qf[2*h2][2], qf[2*h2][3],
                         U(kf.x), U(kf.y));
                mma_tf32(sacc[ni], qf[2*h2+1][0], qf[2*h2+1][1], qf[2*h2+1][2], qf[2*h2+1][3],
                         U(kf.z), U(kf.w));
            }
        }
        // ---- + rel-pos bias from smem table ----
        {
            const int base0 = Cb0 - (k0 >> 5) * 63;
            const int base1 = Cb1 - (k0 >> 5) * 63;
            #pragma unroll
            for (int ni = 0; ni < 8; ni++) {
                const int off = (ni >> 2) * 63 + 8 * (ni & 3) + 2 * t4;
                sacc[ni][0] += tbl[base0 - off];
                sacc[ni][1] += tbl[base0 - off - 1];
                sacc[ni][2] += tbl[base1 - off];
                sacc[ni][3] += tbl[base1 - off - 1];
            }
        }

        // ---- online softmax ----
        float vmax0 = -1e30f, vmax1 = -1e30f;
        #pragma unroll
        for (int ni = 0; ni < 8; ni++) {
            vmax0 = fmaxf(vmax0, fmaxf(sacc[ni][0], sacc[ni][1]));
            vmax1 = fmaxf(vmax1, fmaxf(sacc[ni][2], sacc[ni][3]));
        }
        #pragma unroll
        for (int o = 1; o <= 2; o <<= 1) {
            vmax0 = fmaxf(vmax0, __shfl_xor_sync(0xffffffffu, vmax0, o));
            vmax1 = fmaxf(vmax1, __shfl_xor_sync(0xffffffffu, vmax1, o));
        }
        const float nm0 = fmaxf(m0, vmax0);
        const float nm1 = fmaxf(m1, vmax1);
        const float corr0 = __expf(m0 - nm0);
        const float corr1 = __expf(m1 - nm1);
        m0 = nm0; m1 = nm1;
        float rs0 = 0.0f, rs1 = 0.0f;

        __syncwarp();
        #pragma unroll
        for (int ni = 0; ni < 8; ni++) {
            const float p0 = __expf(sacc[ni][0] - m0);
            const float p1 = __expf(sacc[ni][1] - m0);
            const float p2 = __expf(sacc[ni][2] - m1);
            const float p3 = __expf(sacc[ni][3] - m1);
            rs0 += p0 + p1; rs1 += p2 + p3;
            const int col = ni * 8 + t4 * 2;
            *(float2*)&Ps[warp][g][col]     = make_float2(to_tf32(p0), to_tf32(p1));
            *(float2*)&Ps[warp][g + 8][col] = make_float2(to_tf32(p2), to_tf32(p3));
        }
        li0 = li0 * corr0 + rs0;
        li1 = li1 * corr1 + rs1;
        #pragma unroll
        for (int ni = 0; ni < 4; ni++) {
            acc_o[ni][0] *= corr0; acc_o[ni][1] *= corr0;
            acc_o[ni][2] *= corr1; acc_o[ni][3] *= corr1;
        }
        __syncwarp();

        // ---- O += P @ V ----
        #pragma unroll
        for (int ks = 0; ks < 8; ks++) {
            const int kk = ks * 8;
            uint32_t a0 = U(Ps[warp][g][kk + t4]);
            uint32_t a1 = U(Ps[warp][g + 8][kk + t4]);
            uint32_t a2 = U(Ps[warp][g][kk + t4 + 4]);
            uint32_t a3 = U(Ps[warp][g + 8][kk + t4 + 4]);
            #pragma unroll
            for (int ni = 0; ni < 4; ni++) {
                const uint32_t b0 = U(Vs[s][kk + t4][ni * 8 + g]);
                const uint32_t b1 = U(Vs[s][kk + t4 + 4][ni * 8 + g]);
                mma_tf32(acc_o[ni], a0, a1, a2, a3, b0, b1);
            }
        }
        __syncthreads();
    }

    // ---- finalize: rounded + k-permuted output (feeds proj-A) ----
    #pragma unroll
    for (int o = 1; o <= 2; o <<= 1) {
        li0 += __shfl_xor_sync(0xffffffffu, li0, o);
        li1 += __shfl_xor_sync(0xffffffffu, li1, o);
    }
    const float inv0 = 1.0f / li0;
    const float inv1 = 1.0f / li1;
    float* o0p = out + ((size_t)(b * SEQ + q0 + wq + g)) * DIM + h * HD;
    float* o1p = o0p + 8 * DIM;
    #pragma unroll
    for (int ni = 0; ni < 4; ni++) {
        const int p = 16 * (t4 & 1) + 2 * ni + (t4 >> 1);
        o0p[p]     = to_tf32(acc_o[ni][0] * inv0);
        o0p[p + 8] = to_tf32(acc_o[ni][1] * inv0);
        o1p[p]     = to_tf32(acc_o[ni][2] * inv1);
        o1p[p + 8] = to_tf32(acc_o[ni][3] * inv1);
    }
}

// ---------------- launch -----------------------------------------------------
extern "C" void kernel_launch(void* const* d_in, const int* in_sizes, int n_in,
                              void* d_out, int out_size)
{
    const float* x      = (const float*)d_in[0];
    const float* table  = (const float*)d_in[2];
    const float* qkv_w  = (const float*)d_in[3];
    const float* qkv_b  = (const float*)d_in[4];
    const float* proj_w = (const float*)d_in[5];
    const float* proj_b = (const float*)d_in[6];
    const float* n1_g   = (const float*)d_in[7];
    const float* n1_b   = (const float*)d_in[8];
    const float* n2_g   = (const float*)d_in[9];
    const float* n2_b   = (const float*)d_in[10];
    const float* fc1_w  = (const float*)d_in[11];
    const float* fc1_b  = (const float*)d_in[12];
    const float* fc2_w  = (const float*)d_in[13];
    const float* fc2_b  = (const float*)d_in[14];
    float* out = (float*)d_out;

    float *h, *qkv, *attnout, *xres, *mlp1, *w;
    cudaGetSymbolAddress((void**)&h,       g_h);
    cudaGetSymbolAddress((void**)&qkv,     g_qkv);
    cudaGetSymbolAddress((void**)&attnout, g_attnout);
    cudaGetSymbolAddress((void**)&xres,    g_xres);
    cudaGetSymbolAddress((void**)&mlp1,    g_mlp1);
    cudaGetSymbolAddress((void**)&w,       g_w);

    dim3 tb(32, 8);
    // 0. transpose + permute + round weights
    cvt_t_kernel<<<dim3(48, 16), tb>>>(qkv_w,  w + W_QKV,  DIM,  3 * DIM);
    cvt_t_kernel<<<dim3(16, 16), tb>>>(proj_w, w + W_PROJ, DIM,  DIM);
    cvt_t_kernel<<<dim3(64, 16), tb>>>(fc1_w,  w + W_FC1,  DIM,  MLPH);
    cvt_t_kernel<<<dim3(16, 64), tb>>>(fc2_w,  w + W_FC2,  MLPH, DIM);
    // 1. h = LN1(x) (rounded, permuted)
    ln_kernel<<<MROWS, 128>>>(x, n1_g, n1_b, h);
    // 2. qkv = round(h @ qkv_w + qkv_b); q,k permuted, v plain
    gemm_tc<EPI_BIAS, 1, 2><<<dim3(12, 64), 256>>>(h, w + W_QKV, qkv_b, nullptr, qkv,
                                                   MROWS, 3 * DIM, DIM);
    // 3. flash attention -> rounded permuted [B, L, C]
    attn_tc_kernel<<<dim3(8, HEADS, BATCH), 256>>>(table, attnout);
    // 4. xres = x + attnout @ proj_w + proj_b  (fp32 plain)
    gemm_tc<EPI_RES, 0, 0><<<dim3(4, 64), 256>>>(attnout, w + W_PROJ, proj_b, x, xres,
                                                 MROWS, DIM, DIM);
    // 5. h = LN2(xres) (rounded, permuted)
    ln_kernel<<<MROWS, 128>>>(xres, n2_g, n2_b, h);
    // 6. mlp1 = round(gelu(h @ fc1_w + fc1_b)) permuted
    gemm_tc<EPI_GELU, 1, 1><<<dim3(16, 64), 256>>>(h, w + W_FC1, fc1_b, nullptr, mlp1,
                                                   MROWS, MLPH, DIM);
    // 7. out = xres + mlp1 @ fc2_w + fc2_b  (fp32 plain)
    gemm_tc<EPI_RES, 0, 0><<<dim3(4, 64), 256>>>(mlp1, w + W_FC2, fc2_b, xres, out,
                                                 MROWS, DIM, MLPH);
}